// round 10
// baseline (speedup 1.0000x reference)
#include <cuda_runtime.h>

typedef unsigned long long ull;

#define NATOMS 1536
#define NSPEC 8
#define HID 64
#define NK 32
#define CUTF 5.0f
#define MAXP ((NATOMS*(NATOMS-1))/2)
#define LOCAL_W (NSPEC*NK)   /* 256 */
#define PI_F 3.14159265358979323846f
#define LOG2E 1.4426950408889634f

// ---- device scratch ----
__device__ float g_acc_pair;
__device__ float g_acc_raw;
__device__ float g_acc_lr;
__device__ int   g_npairs;
__device__ float g_T[NSPEC*NSPEC*HID];
__device__ float g_local[NATOMS*LOCAL_W];
__device__ float g_raw[NATOMS];
__device__ float4 g_pos4[NATOMS];
__device__ unsigned g_pairs[MAXP];

__device__ __forceinline__ float siluf(float x){ return __fdividef(x, 1.f+__expf(-x)); }

__device__ __forceinline__ ull pk2(float lo, float hi){
    ull r; asm("mov.b64 %0,{%1,%2};" : "=l"(r) : "f"(lo), "f"(hi)); return r;
}
__device__ __forceinline__ void upk2(ull v, float& lo, float& hi){
    asm("mov.b64 {%0,%1},%2;" : "=f"(lo), "=f"(hi) : "l"(v));
}
__device__ __forceinline__ void fma2(ull& d, ull a, ull b){
    asm("fma.rn.f32x2 %0,%1,%2,%0;" : "+l"(d) : "l"(a), "l"(b));
}

// ---- k_table: species-pair layer1 table + init + pos4 staging ----
__global__ void k_table(const float* __restrict__ pos,
                        const float* __restrict__ embed, const float* __restrict__ W1,
                        const float* __restrict__ b1){
    if(blockIdx.x==0 && threadIdx.x==0){
        g_acc_pair=0.f; g_acc_raw=0.f; g_acc_lr=0.f; g_npairs=0;
    }
    int t=blockIdx.x*64+threadIdx.x;
    if(t<NATOMS) g_pos4[t]=make_float4(pos[3*t],pos[3*t+1],pos[3*t+2],0.f);
    int si=blockIdx.x>>3, sj=blockIdx.x&7, c=threadIdx.x;
    float acc=b1[c];
    for(int m=0;m<32;m++){
        float a=embed[si*32+m], b=embed[sj*32+m];
        acc += (a+b)*W1[(32+m)*HID+c];
        acc += (a*b)*W1[(64+m)*HID+c];
    }
    g_T[(si*NSPEC+sj)*HID+c]=acc;
}

// ---- k_local: 4 atoms/block, 2 warps per atom, ballot-compacted neighbor scan ----
#define JL_CAP 768
__global__ void __launch_bounds__(256) k_local(const float* __restrict__ pos,
                                               const int* __restrict__ species){
    __shared__ float4 sp[NATOMS];              // 24KB
    __shared__ unsigned char ssp[NATOMS];      // 1.5KB
    __shared__ float loc[4][2][LOCAL_W];       // 8KB
    __shared__ unsigned short jl[8][JL_CAP];   // 12KB
    __shared__ int pcnt[8];
    __shared__ int poff[8];
    __shared__ int pbase;
    int tid=threadIdx.x, lane=tid&31, w=tid>>5;
    int a=w>>1, half=w&1;
    int i=blockIdx.x*4+a;
    for(int t=tid;t<NATOMS;t+=256){
        sp[t]=make_float4(pos[3*t],pos[3*t+1],pos[3*t+2],0.f);
        ssp[t]=(unsigned char)species[t];
    }
    for(int t=tid;t<4*2*LOCAL_W;t+=256) (&loc[0][0][0])[t]=0.f;
    __syncthreads();
    float4 pi=sp[i];
    // ---- phase A: lane-parallel cutoff test + compaction ----
    int cnt=0, cgt=0;
    int jbase=half*768;
    for(int t=0;t<768;t+=32){
        int j=jbase+t+lane;
        float4 pj=sp[j];
        float dx=pi.x-pj.x, dy=pi.y-pj.y, dz=pi.z-pj.z;
        float d2=dx*dx+dy*dy+dz*dz+1e-12f;
        bool v = (d2 < CUTF*CUTF) && (j!=i);
        unsigned m = __ballot_sync(0xffffffffu, v);
        if(v) jl[w][cnt + __popc(m & ((1u<<lane)-1u))] = (unsigned short)j;
        cnt += __popc(m);
        cgt += __popc(__ballot_sync(0xffffffffu, v && (j>i)));
    }
    // ---- phase B: 32-wide rbf over survivors ----
    const float C2=-4.0f*LOG2E;
    const float ck=(CUTF/(NK-1))*(float)lane;
    float* myloc = loc[a][half];
    for(int t=0;t<cnt;t++){
        int j=jl[w][t];
        float4 pj=sp[j];
        float dx=pi.x-pj.x, dy=pi.y-pj.y, dz=pi.z-pj.z;
        float d=sqrtf(dx*dx+dy*dy+dz*dz+1e-12f);
        float cut=0.5f*(__cosf(PI_F*(d*(1.f/CUTF)))+1.f);
        float tt=d-ck;
        myloc[ssp[j]*NK+lane] += exp2f(C2*tt*tt)*cut;
    }
    if(lane==0) pcnt[w]=cgt;
    __syncthreads();
    if(tid==0){
        int tot=0;
        #pragma unroll
        for(int gg=0;gg<8;gg++){ poff[gg]=tot; tot+=pcnt[gg]; }
        pbase = tot ? atomicAdd(&g_npairs, tot) : 0;
    }
    __syncthreads();
    {   // pairs = suffix of the sorted survivor list (j>i)
        int base=pbase+poff[w];
        int off=cnt-cgt;
        unsigned hi=((unsigned)i)<<11;
        unsigned sihi=((unsigned)ssp[i])<<3;
        for(int t=lane;t<cgt;t+=32){
            unsigned j=jl[w][off+t];
            g_pairs[base+t]= ((sihi|(unsigned)ssp[j])<<22) | hi | j;
        }
    }
    for(int t=tid;t<4*LOCAL_W;t+=256){
        int aa=t>>8, m=t&255;
        g_local[(blockIdx.x*4+aa)*LOCAL_W+m]=loc[aa][0][m]+loc[aa][1][m];
    }
}

// ---- k_cmlp: 16-atom tile fused charge MLP ----
#define CT_M 16
__global__ void __launch_bounds__(256) k_cmlp(const int* __restrict__ species,
    const float* __restrict__ embed, const float* __restrict__ tc,
    const float* __restrict__ cW1, const float* __restrict__ cb1,
    const float* __restrict__ cW2, const float* __restrict__ cb2,
    const float* __restrict__ cW3, const float* __restrict__ cb3,
    const float* __restrict__ charge_scale, const float* __restrict__ atom_bias){
    __shared__ float xs[CT_M][292];
    __shared__ float hs[CT_M][64];
    __shared__ float vs[CT_M][64];
    int tid=threadIdx.x, c=tid&63, sub=tid>>6;
    int base=blockIdx.x*CT_M;
    for(int idx=tid; idx<CT_M*256; idx+=256){
        int a=idx>>8, m=idx&255;
        xs[a][m]=g_local[(base+a)*LOCAL_W+m];
    }
    for(int idx=tid; idx<CT_M*32; idx+=256){
        int a=idx>>5, m=idx&31;
        xs[a][256+m]=embed[species[base+a]*32+m];
    }
    if(tid<CT_M) xs[tid][288]=tc[0];
    __syncthreads();
    int a0=sub*4;
    float acc[4];
    { float b=cb1[c]; acc[0]=b; acc[1]=b; acc[2]=b; acc[3]=b; }
    for(int m=0;m<288;m+=4){
        float w0=__ldg(&cW1[(m+0)*HID+c]);
        float w1=__ldg(&cW1[(m+1)*HID+c]);
        float w2=__ldg(&cW1[(m+2)*HID+c]);
        float w3=__ldg(&cW1[(m+3)*HID+c]);
        #pragma unroll
        for(int aa=0;aa<4;aa++){
            float4 x=*(const float4*)&xs[a0+aa][m];
            acc[aa]+=x.x*w0+x.y*w1+x.z*w2+x.w*w3;
        }
    }
    {
        float w=__ldg(&cW1[288*HID+c]);
        #pragma unroll
        for(int aa=0;aa<4;aa++) acc[aa]+=xs[a0+aa][288]*w;
    }
    #pragma unroll
    for(int aa=0;aa<4;aa++) hs[a0+aa][c]=siluf(acc[aa]);
    __syncthreads();
    float acc2[4];
    { float b=cb2[c]; acc2[0]=b; acc2[1]=b; acc2[2]=b; acc2[3]=b; }
    for(int m=0;m<HID;m+=4){
        float w0=__ldg(&cW2[(m+0)*HID+c]);
        float w1=__ldg(&cW2[(m+1)*HID+c]);
        float w2=__ldg(&cW2[(m+2)*HID+c]);
        float w3=__ldg(&cW2[(m+3)*HID+c]);
        #pragma unroll
        for(int aa=0;aa<4;aa++){
            float4 h=*(const float4*)&hs[a0+aa][m];
            acc2[aa]+=h.x*w0+h.y*w1+h.z*w2+h.w*w3;
        }
    }
    float w3v=__ldg(&cW3[c]);
    #pragma unroll
    for(int aa=0;aa<4;aa++) vs[a0+aa][c]=siluf(acc2[aa])*w3v;
    __syncthreads();
    if(tid<CT_M){
        float s=0.f;
        const float4* v4=(const float4*)vs[tid];
        #pragma unroll
        for(int t=0;t<16;t++){ float4 v=v4[t]; s+=v.x+v.y+v.z+v.w; }
        float raw=(s+cb3[0])*charge_scale[0];
        g_raw[base+tid]=raw;
        float ab=atom_bias[species[base+tid]];
        #pragma unroll
        for(int off=8;off;off>>=1){
            raw+=__shfl_down_sync(0x0000ffffu,raw,off,16);
            ab +=__shfl_down_sync(0x0000ffffu,ab ,off,16);
        }
        if(tid==0){
            atomicAdd(&g_acc_raw, raw);
            atomicAdd(&g_acc_pair, ab);
        }
    }
}

// ---- k_pair: lane=pair (R4 dataflow), two-pass L1 + two-pass L2 -> <=128 regs ----
__global__ void __launch_bounds__(128,4) k_pair(
    const float* __restrict__ W1, const float* __restrict__ b2g,
    const float* __restrict__ W2, const float* __restrict__ W3,
    const float* __restrict__ b3g){
    __shared__ float sW1[NK*HID];         // 8KB
    __shared__ float sW2[HID*HID];        // 16KB
    __shared__ float sT[NSPEC*NSPEC*HID]; // 16KB
    __shared__ float sW3[HID];
    __shared__ ull   sB2[HID/2];
    int tid=threadIdx.x;
    for(int t=tid;t<NK*HID/4;t+=128)  ((float4*)sW1)[t]=((const float4*)W1)[t];
    for(int t=tid;t<HID*HID/4;t+=128) ((float4*)sW2)[t]=((const float4*)W2)[t];
    for(int t=tid;t<NSPEC*NSPEC*HID/4;t+=128) ((float4*)sT)[t]=((const float4*)g_T)[t];
    if(tid<HID)   sW3[tid]=W3[tid];
    if(tid<HID/2) sB2[tid]=pk2(b2g[2*tid],b2g[2*tid+1]);
    __syncthreads();
    float b3=b3g[0];
    int np=g_npairs;
    int lane=tid&31;
    int gw=(blockIdx.x*128+tid)>>5;
    int nw=(gridDim.x*128)>>5;
    const float C2=-4.0f*LOG2E;
    const float dk=CUTF/(NK-1);
    float eacc=0.f;
    for(int base=gw*32; base<np; base+=nw*32){
        int p=base+lane;
        bool act = p<np;
        unsigned pr = __ldg(&g_pairs[act? p : (np-1)]);
        int spidx = (int)(pr>>22);
        int i=(int)((pr>>11)&2047u), j=(int)(pr&2047u);
        float4 pi=__ldg(&g_pos4[i]);
        float4 pj=__ldg(&g_pos4[j]);
        float dx=pi.x-pj.x, dy=pi.y-pj.y, dz=pi.z-pj.z;
        float d=sqrtf(dx*dx+dy*dy+dz*dz+1e-12f);
        float cut = act ? 0.5f*(__cosf(PI_F*(d*(1.f/CUTF)))+1.f) : 0.f;
        // ---- layer 1: two 32-channel passes, acc[16] live; h packed in 32 ull ----
        ull h[32];
        #pragma unroll
        for(int half=0;half<2;half++){
            ull acc[16];
            const ulonglong2* Tr=(const ulonglong2*)&sT[spidx*HID + half*32];
            #pragma unroll
            for(int q=0;q<8;q++){
                ulonglong2 t=Tr[q];
                acc[2*q]=t.x; acc[2*q+1]=t.y;
            }
            #pragma unroll 4
            for(int k=0;k<NK;k++){
                float t=d-(float)k*dk;
                float r=exp2f(C2*t*t);
                ull rd=pk2(r,r);
                const ulonglong2* wr=(const ulonglong2*)&sW1[k*HID + half*32];
                #pragma unroll
                for(int q=0;q<8;q++){
                    ulonglong2 wv=wr[q];
                    fma2(acc[2*q],   rd, wv.x);
                    fma2(acc[2*q+1], rd, wv.y);
                }
            }
            #pragma unroll
            for(int q=0;q<16;q++){
                float h0,h1; upk2(acc[q],h0,h1);
                h[half*16+q]=pk2(siluf(h0),siluf(h1));
            }
        }
        // ---- layer 2: two 32-channel passes, acc2[16] live, h streamed ----
        float e=b3;
        #pragma unroll
        for(int pass=0;pass<2;pass++){
            ull acc2[16];
            #pragma unroll
            for(int q=0;q<16;q++) acc2[q]=sB2[pass*16+q];
            #pragma unroll
            for(int mq=0;mq<32;mq++){
                float h0,h1; upk2(h[mq],h0,h1);
                ull hd0=pk2(h0,h0), hd1=pk2(h1,h1);
                const ulonglong2* wr0=(const ulonglong2*)&sW2[(2*mq)*HID + pass*32];
                const ulonglong2* wr1=(const ulonglong2*)&sW2[(2*mq+1)*HID + pass*32];
                #pragma unroll
                for(int q=0;q<8;q++){
                    ulonglong2 w0=wr0[q];
                    ulonglong2 w1=wr1[q];
                    fma2(acc2[2*q],   hd0, w0.x);
                    fma2(acc2[2*q+1], hd0, w0.y);
                    fma2(acc2[2*q],   hd1, w1.x);
                    fma2(acc2[2*q+1], hd1, w1.y);
                }
            }
            #pragma unroll
            for(int q=0;q<16;q++){
                float a,b; upk2(acc2[q],a,b);
                e += siluf(a)*sW3[pass*32+2*q] + siluf(b)*sW3[pass*32+2*q+1];
            }
        }
        eacc += e*cut;
    }
    #pragma unroll
    for(int off=16;off;off>>=1) eacc += __shfl_down_sync(0xffffffffu, eacc, off);
    if(lane==0) atomicAdd(&g_acc_pair, eacc);
}

// ---- k_coul: 64x64 tiled triangle (300 blocks) + charge normalization/output ----
#define CTILE 64
#define NT (NATOMS/CTILE)
__global__ void __launch_bounds__(CTILE) k_coul(const float* __restrict__ pos,
    const float* __restrict__ tc, const float* __restrict__ soft_raw,
    float* __restrict__ out){
    __shared__ float4 sp[CTILE];
    __shared__ float  sq[CTILE];
    __shared__ float  red[CTILE];
    int b=blockIdx.x;
    int bi=0;
    {   int bb=b;
        while(bb >= NT-bi){ bb-=NT-bi; bi++; }
        b=bb;
    }
    int bj=bi+b;
    int t=threadIdx.x;
    float mu = g_acc_raw*(1.f/NATOMS);
    float qadd = tc[0]*(1.f/NATOMS) - mu;
    int i = bi*CTILE+t;
    float qi = g_raw[i]+qadd;
    float4 piv = make_float4(pos[3*i],pos[3*i+1],pos[3*i+2],0.f);
    {
        int j = bj*CTILE+t;
        sp[t]=make_float4(pos[3*j],pos[3*j+1],pos[3*j+2],0.f);
        sq[t]=g_raw[j]+qadd;
    }
    __syncthreads();
    float soft=log1pf(__expf(soft_raw[0]))+0.001f;
    float s2=soft*soft+1e-12f;
    float acc=0.f;
    if(bi==bj){
        out[1+i]=qi;
        for(int jj=t+1;jj<CTILE;jj++){
            float4 pj=sp[jj];
            float dx=piv.x-pj.x,dy=piv.y-pj.y,dz=piv.z-pj.z;
            acc += sq[jj]*rsqrtf(dx*dx+dy*dy+dz*dz+s2);
        }
    } else {
        for(int jj=0;jj<CTILE;jj++){
            float4 pj=sp[jj];
            float dx=piv.x-pj.x,dy=piv.y-pj.y,dz=piv.z-pj.z;
            acc += sq[jj]*rsqrtf(dx*dx+dy*dy+dz*dz+s2);
        }
    }
    red[t]=acc*qi;
    __syncthreads();
    for(int off=CTILE/2;off;off>>=1){ if(t<off) red[t]+=red[t+off]; __syncthreads(); }
    if(t==0) atomicAdd(&g_acc_lr, red[0]);
}

__global__ void k_final(const float* __restrict__ cs, float* __restrict__ out){
    out[0]=g_acc_pair + cs[0]*g_acc_lr;
}

extern "C" void kernel_launch(void* const* d_in, const int* in_sizes, int n_in,
                              void* d_out, int out_size){
    const int*   species      =(const int*)  d_in[0];
    const float* pos          =(const float*)d_in[1];
    const float* tc           =(const float*)d_in[2];
    const float* embed        =(const float*)d_in[3];
    const float* W1           =(const float*)d_in[4];
    const float* b1           =(const float*)d_in[5];
    const float* W2           =(const float*)d_in[6];
    const float* b2           =(const float*)d_in[7];
    const float* W3           =(const float*)d_in[8];
    const float* b3           =(const float*)d_in[9];
    const float* atom_bias    =(const float*)d_in[10];
    const float* cW1          =(const float*)d_in[11];
    const float* cb1          =(const float*)d_in[12];
    const float* cW2          =(const float*)d_in[13];
    const float* cb2          =(const float*)d_in[14];
    const float* cW3          =(const float*)d_in[15];
    const float* cb3          =(const float*)d_in[16];
    const float* charge_scale =(const float*)d_in[17];
    const float* coulomb_scale=(const float*)d_in[18];
    const float* soft_raw     =(const float*)d_in[19];
    float* out=(float*)d_out;

    k_table <<<64,64>>>(pos,embed,W1,b1);
    k_local <<<NATOMS/4,256>>>(pos,species);
    k_cmlp  <<<NATOMS/CT_M,256>>>(species,embed,tc,cW1,cb1,cW2,cb2,cW3,cb3,charge_scale,atom_bias);
    k_pair  <<<592,128>>>(W1,b2,W2,W3,b3);
    k_coul  <<<NT*(NT+1)/2,CTILE>>>(pos,tc,soft_raw,out);
    k_final <<<1,1>>>(coulomb_scale,out);
}

// round 11
// speedup vs baseline: 1.2344x; 1.2344x over previous
#include <cuda_runtime.h>

typedef unsigned long long ull;

#define NATOMS 1536
#define NSPEC 8
#define HID 64
#define NK 32
#define CUTF 5.0f
#define MAXP ((NATOMS*(NATOMS-1))/2)
#define LOCAL_W (NSPEC*NK)   /* 256 */
#define PI_F 3.14159265358979323846f
#define LOG2E 1.4426950408889634f

// ---- device scratch ----
__device__ float g_acc_pair;
__device__ float g_acc_raw;
__device__ float g_acc_lr;
__device__ int   g_npairs;
__device__ float g_T[NSPEC*NSPEC*HID];
__device__ float g_local[NATOMS*LOCAL_W];
__device__ float g_raw[NATOMS];
__device__ float4 g_pos4[NATOMS];
__device__ unsigned g_pairs[MAXP];

__device__ __forceinline__ float siluf(float x){ return __fdividef(x, 1.f+__expf(-x)); }

__device__ __forceinline__ ull pk2(float lo, float hi){
    ull r; asm("mov.b64 %0,{%1,%2};" : "=l"(r) : "f"(lo), "f"(hi)); return r;
}
__device__ __forceinline__ void upk2(ull v, float& lo, float& hi){
    asm("mov.b64 {%0,%1},%2;" : "=f"(lo), "=f"(hi) : "l"(v));
}
__device__ __forceinline__ void fma2(ull& d, ull a, ull b){
    asm("fma.rn.f32x2 %0,%1,%2,%0;" : "+l"(d) : "l"(a), "l"(b));
}

// ---- k_table: species-pair layer1 table + init + pos4 staging ----
__global__ void k_table(const float* __restrict__ pos,
                        const float* __restrict__ embed, const float* __restrict__ W1,
                        const float* __restrict__ b1){
    if(blockIdx.x==0 && threadIdx.x==0){
        g_acc_pair=0.f; g_acc_raw=0.f; g_acc_lr=0.f; g_npairs=0;
    }
    int t=blockIdx.x*64+threadIdx.x;
    if(t<NATOMS) g_pos4[t]=make_float4(pos[3*t],pos[3*t+1],pos[3*t+2],0.f);
    int si=blockIdx.x>>3, sj=blockIdx.x&7, c=threadIdx.x;
    float acc=b1[c];
    for(int m=0;m<32;m++){
        float a=embed[si*32+m], b=embed[sj*32+m];
        acc += (a+b)*W1[(32+m)*HID+c];
        acc += (a*b)*W1[(64+m)*HID+c];
    }
    g_T[(si*NSPEC+sj)*HID+c]=acc;
}

// ---- k_local: 4 atoms/block, 2 warps per atom, ballot-compacted neighbor scan ----
#define JL_CAP 768
__global__ void __launch_bounds__(256) k_local(const float* __restrict__ pos,
                                               const int* __restrict__ species){
    __shared__ float4 sp[NATOMS];              // 24KB
    __shared__ unsigned char ssp[NATOMS];      // 1.5KB
    __shared__ float loc[4][2][LOCAL_W];       // 8KB
    __shared__ unsigned short jl[8][JL_CAP];   // 12KB
    __shared__ int pcnt[8];
    __shared__ int poff[8];
    __shared__ int pbase;
    int tid=threadIdx.x, lane=tid&31, w=tid>>5;
    int a=w>>1, half=w&1;
    int i=blockIdx.x*4+a;
    for(int t=tid;t<NATOMS;t+=256){
        sp[t]=make_float4(pos[3*t],pos[3*t+1],pos[3*t+2],0.f);
        ssp[t]=(unsigned char)species[t];
    }
    for(int t=tid;t<4*2*LOCAL_W;t+=256) (&loc[0][0][0])[t]=0.f;
    __syncthreads();
    float4 pi=sp[i];
    int cnt=0, cgt=0;
    int jbase=half*768;
    for(int t=0;t<768;t+=32){
        int j=jbase+t+lane;
        float4 pj=sp[j];
        float dx=pi.x-pj.x, dy=pi.y-pj.y, dz=pi.z-pj.z;
        float d2=dx*dx+dy*dy+dz*dz+1e-12f;
        bool v = (d2 < CUTF*CUTF) && (j!=i);
        unsigned m = __ballot_sync(0xffffffffu, v);
        if(v) jl[w][cnt + __popc(m & ((1u<<lane)-1u))] = (unsigned short)j;
        cnt += __popc(m);
        cgt += __popc(__ballot_sync(0xffffffffu, v && (j>i)));
    }
    const float C2=-4.0f*LOG2E;
    const float ck=(CUTF/(NK-1))*(float)lane;
    float* myloc = loc[a][half];
    for(int t=0;t<cnt;t++){
        int j=jl[w][t];
        float4 pj=sp[j];
        float dx=pi.x-pj.x, dy=pi.y-pj.y, dz=pi.z-pj.z;
        float d=sqrtf(dx*dx+dy*dy+dz*dz+1e-12f);
        float cut=0.5f*(__cosf(PI_F*(d*(1.f/CUTF)))+1.f);
        float tt=d-ck;
        myloc[ssp[j]*NK+lane] += exp2f(C2*tt*tt)*cut;
    }
    if(lane==0) pcnt[w]=cgt;
    __syncthreads();
    if(tid==0){
        int tot=0;
        #pragma unroll
        for(int gg=0;gg<8;gg++){ poff[gg]=tot; tot+=pcnt[gg]; }
        pbase = tot ? atomicAdd(&g_npairs, tot) : 0;
    }
    __syncthreads();
    {
        int base=pbase+poff[w];
        int off=cnt-cgt;
        unsigned hi=((unsigned)i)<<11;
        unsigned sihi=((unsigned)ssp[i])<<3;
        for(int t=lane;t<cgt;t+=32){
            unsigned j=jl[w][off+t];
            g_pairs[base+t]= ((sihi|(unsigned)ssp[j])<<22) | hi | j;
        }
    }
    for(int t=tid;t<4*LOCAL_W;t+=256){
        int aa=t>>8, m=t&255;
        g_local[(blockIdx.x*4+aa)*LOCAL_W+m]=loc[aa][0][m]+loc[aa][1][m];
    }
}

// ---- k_cmlp: 16-atom tile fused charge MLP ----
#define CT_M 16
__global__ void __launch_bounds__(256) k_cmlp(const int* __restrict__ species,
    const float* __restrict__ embed, const float* __restrict__ tc,
    const float* __restrict__ cW1, const float* __restrict__ cb1,
    const float* __restrict__ cW2, const float* __restrict__ cb2,
    const float* __restrict__ cW3, const float* __restrict__ cb3,
    const float* __restrict__ charge_scale, const float* __restrict__ atom_bias){
    __shared__ float xs[CT_M][292];
    __shared__ float hs[CT_M][64];
    __shared__ float vs[CT_M][64];
    int tid=threadIdx.x, c=tid&63, sub=tid>>6;
    int base=blockIdx.x*CT_M;
    for(int idx=tid; idx<CT_M*256; idx+=256){
        int a=idx>>8, m=idx&255;
        xs[a][m]=g_local[(base+a)*LOCAL_W+m];
    }
    for(int idx=tid; idx<CT_M*32; idx+=256){
        int a=idx>>5, m=idx&31;
        xs[a][256+m]=embed[species[base+a]*32+m];
    }
    if(tid<CT_M) xs[tid][288]=tc[0];
    __syncthreads();
    int a0=sub*4;
    float acc[4];
    { float b=cb1[c]; acc[0]=b; acc[1]=b; acc[2]=b; acc[3]=b; }
    for(int m=0;m<288;m+=4){
        float w0=__ldg(&cW1[(m+0)*HID+c]);
        float w1=__ldg(&cW1[(m+1)*HID+c]);
        float w2=__ldg(&cW1[(m+2)*HID+c]);
        float w3=__ldg(&cW1[(m+3)*HID+c]);
        #pragma unroll
        for(int aa=0;aa<4;aa++){
            float4 x=*(const float4*)&xs[a0+aa][m];
            acc[aa]+=x.x*w0+x.y*w1+x.z*w2+x.w*w3;
        }
    }
    {
        float w=__ldg(&cW1[288*HID+c]);
        #pragma unroll
        for(int aa=0;aa<4;aa++) acc[aa]+=xs[a0+aa][288]*w;
    }
    #pragma unroll
    for(int aa=0;aa<4;aa++) hs[a0+aa][c]=siluf(acc[aa]);
    __syncthreads();
    float acc2[4];
    { float b=cb2[c]; acc2[0]=b; acc2[1]=b; acc2[2]=b; acc2[3]=b; }
    for(int m=0;m<HID;m+=4){
        float w0=__ldg(&cW2[(m+0)*HID+c]);
        float w1=__ldg(&cW2[(m+1)*HID+c]);
        float w2=__ldg(&cW2[(m+2)*HID+c]);
        float w3=__ldg(&cW2[(m+3)*HID+c]);
        #pragma unroll
        for(int aa=0;aa<4;aa++){
            float4 h=*(const float4*)&hs[a0+aa][m];
            acc2[aa]+=h.x*w0+h.y*w1+h.z*w2+h.w*w3;
        }
    }
    float w3v=__ldg(&cW3[c]);
    #pragma unroll
    for(int aa=0;aa<4;aa++) vs[a0+aa][c]=siluf(acc2[aa])*w3v;
    __syncthreads();
    if(tid<CT_M){
        float s=0.f;
        const float4* v4=(const float4*)vs[tid];
        #pragma unroll
        for(int t=0;t<16;t++){ float4 v=v4[t]; s+=v.x+v.y+v.z+v.w; }
        float raw=(s+cb3[0])*charge_scale[0];
        g_raw[base+tid]=raw;
        float ab=atom_bias[species[base+tid]];
        #pragma unroll
        for(int off=8;off;off>>=1){
            raw+=__shfl_down_sync(0x0000ffffu,raw,off,16);
            ab +=__shfl_down_sync(0x0000ffffu,ab ,off,16);
        }
        if(tid==0){
            atomicAdd(&g_acc_raw, raw);
            atomicAdd(&g_acc_pair, ab);
        }
    }
}

// ---- k_pair: R4 verbatim — lane=pair, single-pass L1+L2, 168 regs / 3 blocks ----
__global__ void __launch_bounds__(128,3) k_pair(
    const float* __restrict__ W1, const float* __restrict__ b2g,
    const float* __restrict__ W2, const float* __restrict__ W3,
    const float* __restrict__ b3g){
    __shared__ float sW1[NK*HID];         // 8KB
    __shared__ float sW2[HID*HID];        // 16KB
    __shared__ float sT[NSPEC*NSPEC*HID]; // 16KB
    __shared__ float sW3[HID];
    __shared__ ull   sB2[HID/2];
    int tid=threadIdx.x;
    for(int t=tid;t<NK*HID/4;t+=128)  ((float4*)sW1)[t]=((const float4*)W1)[t];
    for(int t=tid;t<HID*HID/4;t+=128) ((float4*)sW2)[t]=((const float4*)W2)[t];
    for(int t=tid;t<NSPEC*NSPEC*HID/4;t+=128) ((float4*)sT)[t]=((const float4*)g_T)[t];
    if(tid<HID)   sW3[tid]=W3[tid];
    if(tid<HID/2) sB2[tid]=pk2(b2g[2*tid],b2g[2*tid+1]);
    __syncthreads();
    float b3=b3g[0];
    int np=g_npairs;
    int lane=tid&31;
    int gw=(blockIdx.x*128+tid)>>5;
    int nw=(gridDim.x*128)>>5;
    const float C2=-4.0f*LOG2E;
    const float dk=CUTF/(NK-1);
    float eacc=0.f;
    for(int base=gw*32; base<np; base+=nw*32){
        int p=base+lane;
        bool act = p<np;
        unsigned pr = __ldg(&g_pairs[act? p : (np-1)]);
        int spidx = (int)(pr>>22);
        int i=(int)((pr>>11)&2047u), j=(int)(pr&2047u);
        float4 pi=__ldg(&g_pos4[i]);
        float4 pj=__ldg(&g_pos4[j]);
        float dx=pi.x-pj.x, dy=pi.y-pj.y, dz=pi.z-pj.z;
        float d=sqrtf(dx*dx+dy*dy+dz*dz+1e-12f);
        float cut = act ? 0.5f*(__cosf(PI_F*(d*(1.f/CUTF)))+1.f) : 0.f;
        // ---- layer 1 ----
        ull acc[32];
        const float4* Tr=(const float4*)&sT[spidx*HID];
        #pragma unroll
        for(int q=0;q<16;q++){
            float4 t=Tr[q];
            acc[2*q]=pk2(t.x,t.y); acc[2*q+1]=pk2(t.z,t.w);
        }
        #pragma unroll 4
        for(int k=0;k<NK;k++){
            float t=d-(float)k*dk;
            float r=exp2f(C2*t*t);
            ull rd=pk2(r,r);
            const ulonglong2* wr=(const ulonglong2*)&sW1[k*HID];
            #pragma unroll
            for(int q=0;q<16;q++){
                ulonglong2 wv=wr[q];
                fma2(acc[2*q],   rd, wv.x);
                fma2(acc[2*q+1], rd, wv.y);
            }
        }
        // ---- silu in place ----
        #pragma unroll
        for(int mq=0;mq<32;mq++){
            float h0,h1; upk2(acc[mq],h0,h1);
            acc[mq]=pk2(siluf(h0),siluf(h1));
        }
        // ---- layer 2 single pass ----
        ull acc2[32];
        #pragma unroll
        for(int q=0;q<32;q++) acc2[q]=sB2[q];
        #pragma unroll
        for(int mq=0;mq<32;mq++){
            float h0,h1; upk2(acc[mq],h0,h1);
            ull hd0=pk2(h0,h0), hd1=pk2(h1,h1);
            const ulonglong2* wr0=(const ulonglong2*)&sW2[(2*mq)*HID];
            const ulonglong2* wr1=(const ulonglong2*)&sW2[(2*mq+1)*HID];
            #pragma unroll
            for(int q=0;q<16;q++){
                ulonglong2 w0=wr0[q];
                ulonglong2 w1=wr1[q];
                fma2(acc2[2*q],   hd0, w0.x);
                fma2(acc2[2*q+1], hd0, w0.y);
                fma2(acc2[2*q],   hd1, w1.x);
                fma2(acc2[2*q+1], hd1, w1.y);
            }
        }
        // ---- epilogue ----
        float e=b3;
        #pragma unroll
        for(int q=0;q<32;q++){
            float a,b; upk2(acc2[q],a,b);
            e += siluf(a)*sW3[2*q] + siluf(b)*sW3[2*q+1];
        }
        eacc += e*cut;
    }
    #pragma unroll
    for(int off=16;off;off>>=1) eacc += __shfl_down_sync(0xffffffffu, eacc, off);
    if(lane==0) atomicAdd(&g_acc_pair, eacc);
}

// ---- k_coul: 128x128 tiled triangle + charge normalization/output ----
#define CTILE 128
#define NT (NATOMS/CTILE)
__global__ void __launch_bounds__(CTILE) k_coul(const float* __restrict__ pos,
    const float* __restrict__ tc, const float* __restrict__ soft_raw,
    float* __restrict__ out){
    __shared__ float4 sp[CTILE];
    __shared__ float  sq[CTILE];
    __shared__ float  red[CTILE];
    int b=blockIdx.x;
    int bi=0;
    {   int bb=b;
        while(bb >= NT-bi){ bb-=NT-bi; bi++; }
        b=bb;
    }
    int bj=bi+b;
    int t=threadIdx.x;
    float mu = g_acc_raw*(1.f/NATOMS);
    float qadd = tc[0]*(1.f/NATOMS) - mu;
    int i = bi*CTILE+t;
    float qi = g_raw[i]+qadd;
    float4 piv = make_float4(pos[3*i],pos[3*i+1],pos[3*i+2],0.f);
    {
        int j = bj*CTILE+t;
        sp[t]=make_float4(pos[3*j],pos[3*j+1],pos[3*j+2],0.f);
        sq[t]=g_raw[j]+qadd;
    }
    __syncthreads();
    float soft=log1pf(__expf(soft_raw[0]))+0.001f;
    float s2=soft*soft+1e-12f;
    float acc=0.f;
    if(bi==bj){
        out[1+i]=qi;
        for(int jj=t+1;jj<CTILE;jj++){
            float4 pj=sp[jj];
            float dx=piv.x-pj.x,dy=piv.y-pj.y,dz=piv.z-pj.z;
            acc += sq[jj]*rsqrtf(dx*dx+dy*dy+dz*dz+s2);
        }
    } else {
        for(int jj=0;jj<CTILE;jj++){
            float4 pj=sp[jj];
            float dx=piv.x-pj.x,dy=piv.y-pj.y,dz=piv.z-pj.z;
            acc += sq[jj]*rsqrtf(dx*dx+dy*dy+dz*dz+s2);
        }
    }
    red[t]=acc*qi;
    __syncthreads();
    for(int off=CTILE/2;off;off>>=1){ if(t<off) red[t]+=red[t+off]; __syncthreads(); }
    if(t==0) atomicAdd(&g_acc_lr, red[0]);
}

__global__ void k_final(const float* __restrict__ cs, float* __restrict__ out){
    out[0]=g_acc_pair + cs[0]*g_acc_lr;
}

extern "C" void kernel_launch(void* const* d_in, const int* in_sizes, int n_in,
                              void* d_out, int out_size){
    const int*   species      =(const int*)  d_in[0];
    const float* pos          =(const float*)d_in[1];
    const float* tc           =(const float*)d_in[2];
    const float* embed        =(const float*)d_in[3];
    const float* W1           =(const float*)d_in[4];
    const float* b1           =(const float*)d_in[5];
    const float* W2           =(const float*)d_in[6];
    const float* b2           =(const float*)d_in[7];
    const float* W3           =(const float*)d_in[8];
    const float* b3           =(const float*)d_in[9];
    const float* atom_bias    =(const float*)d_in[10];
    const float* cW1          =(const float*)d_in[11];
    const float* cb1          =(const float*)d_in[12];
    const float* cW2          =(const float*)d_in[13];
    const float* cb2          =(const float*)d_in[14];
    const float* cW3          =(const float*)d_in[15];
    const float* cb3          =(const float*)d_in[16];
    const float* charge_scale =(const float*)d_in[17];
    const float* coulomb_scale=(const float*)d_in[18];
    const float* soft_raw     =(const float*)d_in[19];
    float* out=(float*)d_out;

    static cudaStream_t s2;
    static cudaEvent_t evFork, evJoin;
    static int init_done = 0;
    if(!init_done){
        cudaStreamCreateWithFlags(&s2, cudaStreamNonBlocking);
        cudaEventCreateWithFlags(&evFork, cudaEventDisableTiming);
        cudaEventCreateWithFlags(&evJoin, cudaEventDisableTiming);
        init_done = 1;
    }

    // main stream: table -> local -> [fork] -> pair -> [join] -> final
    k_table <<<64,64>>>(pos,embed,W1,b1);
    k_local <<<NATOMS/4,256>>>(pos,species);
    cudaEventRecord(evFork, 0);

    // side stream: cmlp -> coul (independent of k_pair)
    cudaStreamWaitEvent(s2, evFork, 0);
    k_cmlp  <<<NATOMS/CT_M,256,0,s2>>>(species,embed,tc,cW1,cb1,cW2,cb2,cW3,cb3,charge_scale,atom_bias);
    k_coul  <<<NT*(NT+1)/2,CTILE,0,s2>>>(pos,tc,soft_raw,out);
    cudaEventRecord(evJoin, s2);

    k_pair  <<<444,128>>>(W1,b2,W2,W3,b3);
    cudaStreamWaitEvent(0, evJoin, 0);
    k_final <<<1,1>>>(coulomb_scale,out);
}

// round 12
// speedup vs baseline: 1.9113x; 1.5483x over previous
#include <cuda_runtime.h>

typedef unsigned long long ull;

#define NATOMS 1536
#define NSPEC 8
#define HID 64
#define NK 32
#define CUTF 5.0f
#define MAXP ((NATOMS*(NATOMS-1))/2)
#define LOCAL_W (NSPEC*NK)   /* 256 */
#define PI_F 3.14159265358979323846f
#define LOG2E 1.4426950408889634f

#define TSAMP 516            /* samples per species combo: d=(m-1)*DLT, m=0..515 */
#define TPAD  520
#define DLT   (5.0f/512.0f)  /* exactly representable */

// ---- device scratch ----
__device__ float g_acc_pair;
__device__ float g_acc_raw;
__device__ float g_acc_lr;
__device__ int   g_npairs;
__device__ float g_T[NSPEC*NSPEC*HID];
__device__ float g_local[NATOMS*LOCAL_W];
__device__ float g_raw[NATOMS];
__device__ float4 g_pos4[NATOMS];
__device__ unsigned g_pairs[MAXP];
__device__ float g_gtab[NSPEC*NSPEC][TPAD];

__device__ __forceinline__ float siluf(float x){ return __fdividef(x, 1.f+__expf(-x)); }

__device__ __forceinline__ ull pk2(float lo, float hi){
    ull r; asm("mov.b64 %0,{%1,%2};" : "=l"(r) : "f"(lo), "f"(hi)); return r;
}
__device__ __forceinline__ void upk2(ull v, float& lo, float& hi){
    asm("mov.b64 {%0,%1},%2;" : "=f"(lo), "=f"(hi) : "l"(v));
}
__device__ __forceinline__ void fma2(ull& d, ull a, ull b){
    asm("fma.rn.f32x2 %0,%1,%2,%0;" : "+l"(d) : "l"(a), "l"(b));
}

// ---- k_table: species-pair layer1 table + init + pos4 staging ----
__global__ void k_table(const float* __restrict__ pos,
                        const float* __restrict__ embed, const float* __restrict__ W1,
                        const float* __restrict__ b1){
    if(blockIdx.x==0 && threadIdx.x==0){
        g_acc_pair=0.f; g_acc_raw=0.f; g_acc_lr=0.f; g_npairs=0;
    }
    int t=blockIdx.x*64+threadIdx.x;
    if(t<NATOMS) g_pos4[t]=make_float4(pos[3*t],pos[3*t+1],pos[3*t+2],0.f);
    int si=blockIdx.x>>3, sj=blockIdx.x&7, c=threadIdx.x;
    float acc=b1[c];
    for(int m=0;m<32;m++){
        float a=embed[si*32+m], b=embed[sj*32+m];
        acc += (a+b)*W1[(32+m)*HID+c];
        acc += (a*b)*W1[(64+m)*HID+c];
    }
    g_T[(si*NSPEC+sj)*HID+c]=acc;
}

// ---- k_local: 4 atoms/block, 2 warps per atom, ballot-compacted neighbor scan ----
#define JL_CAP 768
__global__ void __launch_bounds__(256) k_local(const float* __restrict__ pos,
                                               const int* __restrict__ species){
    __shared__ float4 sp[NATOMS];              // 24KB
    __shared__ unsigned char ssp[NATOMS];      // 1.5KB
    __shared__ float loc[4][2][LOCAL_W];       // 8KB
    __shared__ unsigned short jl[8][JL_CAP];   // 12KB
    __shared__ int pcnt[8];
    __shared__ int poff[8];
    __shared__ int pbase;
    int tid=threadIdx.x, lane=tid&31, w=tid>>5;
    int a=w>>1, half=w&1;
    int i=blockIdx.x*4+a;
    for(int t=tid;t<NATOMS;t+=256){
        sp[t]=make_float4(pos[3*t],pos[3*t+1],pos[3*t+2],0.f);
        ssp[t]=(unsigned char)species[t];
    }
    for(int t=tid;t<4*2*LOCAL_W;t+=256) (&loc[0][0][0])[t]=0.f;
    __syncthreads();
    float4 pi=sp[i];
    int cnt=0, cgt=0;
    int jbase=half*768;
    for(int t=0;t<768;t+=32){
        int j=jbase+t+lane;
        float4 pj=sp[j];
        float dx=pi.x-pj.x, dy=pi.y-pj.y, dz=pi.z-pj.z;
        float d2=dx*dx+dy*dy+dz*dz+1e-12f;
        bool v = (d2 < CUTF*CUTF) && (j!=i);
        unsigned m = __ballot_sync(0xffffffffu, v);
        if(v) jl[w][cnt + __popc(m & ((1u<<lane)-1u))] = (unsigned short)j;
        cnt += __popc(m);
        cgt += __popc(__ballot_sync(0xffffffffu, v && (j>i)));
    }
    const float C2=-4.0f*LOG2E;
    const float ck=(CUTF/(NK-1))*(float)lane;
    float* myloc = loc[a][half];
    for(int t=0;t<cnt;t++){
        int j=jl[w][t];
        float4 pj=sp[j];
        float dx=pi.x-pj.x, dy=pi.y-pj.y, dz=pi.z-pj.z;
        float d=sqrtf(dx*dx+dy*dy+dz*dz+1e-12f);
        float cut=0.5f*(__cosf(PI_F*(d*(1.f/CUTF)))+1.f);
        float tt=d-ck;
        myloc[ssp[j]*NK+lane] += exp2f(C2*tt*tt)*cut;
    }
    if(lane==0) pcnt[w]=cgt;
    __syncthreads();
    if(tid==0){
        int tot=0;
        #pragma unroll
        for(int gg=0;gg<8;gg++){ poff[gg]=tot; tot+=pcnt[gg]; }
        pbase = tot ? atomicAdd(&g_npairs, tot) : 0;
    }
    __syncthreads();
    {
        int base=pbase+poff[w];
        int off=cnt-cgt;
        unsigned hi=((unsigned)i)<<11;
        unsigned sihi=((unsigned)ssp[i])<<3;
        for(int t=lane;t<cgt;t+=32){
            unsigned j=jl[w][off+t];
            g_pairs[base+t]= ((sihi|(unsigned)ssp[j])<<22) | hi | j;
        }
    }
    for(int t=tid;t<4*LOCAL_W;t+=256){
        int aa=t>>8, m=t&255;
        g_local[(blockIdx.x*4+aa)*LOCAL_W+m]=loc[aa][0][m]+loc[aa][1][m];
    }
}

// ---- k_cmlp: 16-atom tile fused charge MLP ----
#define CT_M 16
__global__ void __launch_bounds__(256) k_cmlp(const int* __restrict__ species,
    const float* __restrict__ embed, const float* __restrict__ tc,
    const float* __restrict__ cW1, const float* __restrict__ cb1,
    const float* __restrict__ cW2, const float* __restrict__ cb2,
    const float* __restrict__ cW3, const float* __restrict__ cb3,
    const float* __restrict__ charge_scale, const float* __restrict__ atom_bias){
    __shared__ float xs[CT_M][292];
    __shared__ float hs[CT_M][64];
    __shared__ float vs[CT_M][64];
    int tid=threadIdx.x, c=tid&63, sub=tid>>6;
    int base=blockIdx.x*CT_M;
    for(int idx=tid; idx<CT_M*256; idx+=256){
        int a=idx>>8, m=idx&255;
        xs[a][m]=g_local[(base+a)*LOCAL_W+m];
    }
    for(int idx=tid; idx<CT_M*32; idx+=256){
        int a=idx>>5, m=idx&31;
        xs[a][256+m]=embed[species[base+a]*32+m];
    }
    if(tid<CT_M) xs[tid][288]=tc[0];
    __syncthreads();
    int a0=sub*4;
    float acc[4];
    { float b=cb1[c]; acc[0]=b; acc[1]=b; acc[2]=b; acc[3]=b; }
    for(int m=0;m<288;m+=4){
        float w0=__ldg(&cW1[(m+0)*HID+c]);
        float w1=__ldg(&cW1[(m+1)*HID+c]);
        float w2=__ldg(&cW1[(m+2)*HID+c]);
        float w3=__ldg(&cW1[(m+3)*HID+c]);
        #pragma unroll
        for(int aa=0;aa<4;aa++){
            float4 x=*(const float4*)&xs[a0+aa][m];
            acc[aa]+=x.x*w0+x.y*w1+x.z*w2+x.w*w3;
        }
    }
    {
        float w=__ldg(&cW1[288*HID+c]);
        #pragma unroll
        for(int aa=0;aa<4;aa++) acc[aa]+=xs[a0+aa][288]*w;
    }
    #pragma unroll
    for(int aa=0;aa<4;aa++) hs[a0+aa][c]=siluf(acc[aa]);
    __syncthreads();
    float acc2[4];
    { float b=cb2[c]; acc2[0]=b; acc2[1]=b; acc2[2]=b; acc2[3]=b; }
    for(int m=0;m<HID;m+=4){
        float w0=__ldg(&cW2[(m+0)*HID+c]);
        float w1=__ldg(&cW2[(m+1)*HID+c]);
        float w2=__ldg(&cW2[(m+2)*HID+c]);
        float w3=__ldg(&cW2[(m+3)*HID+c]);
        #pragma unroll
        for(int aa=0;aa<4;aa++){
            float4 h=*(const float4*)&hs[a0+aa][m];
            acc2[aa]+=h.x*w0+h.y*w1+h.z*w2+h.w*w3;
        }
    }
    float w3v=__ldg(&cW3[c]);
    #pragma unroll
    for(int aa=0;aa<4;aa++) vs[a0+aa][c]=siluf(acc2[aa])*w3v;
    __syncthreads();
    if(tid<CT_M){
        float s=0.f;
        const float4* v4=(const float4*)vs[tid];
        #pragma unroll
        for(int t=0;t<16;t++){ float4 v=v4[t]; s+=v.x+v.y+v.z+v.w; }
        float raw=(s+cb3[0])*charge_scale[0];
        g_raw[base+tid]=raw;
        float ab=atom_bias[species[base+tid]];
        #pragma unroll
        for(int off=8;off;off>>=1){
            raw+=__shfl_down_sync(0x0000ffffu,raw,off,16);
            ab +=__shfl_down_sync(0x0000ffffu,ab ,off,16);
        }
        if(tid==0){
            atomicAdd(&g_acc_raw, raw);
            atomicAdd(&g_acc_pair, ab);
        }
    }
}

// ---- k_tab2: build pair-energy table g(d, si, sj) = (MLP(d,si,sj)+b3)*cut(d) ----
// one sample per lane; same MLP body as the old k_pair.
__global__ void __launch_bounds__(128,3) k_tab2(
    const float* __restrict__ W1, const float* __restrict__ b2g,
    const float* __restrict__ W2, const float* __restrict__ W3,
    const float* __restrict__ b3g){
    __shared__ float sW1[NK*HID];         // 8KB
    __shared__ float sW2[HID*HID];        // 16KB
    __shared__ float sT[NSPEC*NSPEC*HID]; // 16KB
    __shared__ float sW3[HID];
    __shared__ ull   sB2[HID/2];
    int tid=threadIdx.x;
    for(int t=tid;t<NK*HID/4;t+=128)  ((float4*)sW1)[t]=((const float4*)W1)[t];
    for(int t=tid;t<HID*HID/4;t+=128) ((float4*)sW2)[t]=((const float4*)W2)[t];
    for(int t=tid;t<NSPEC*NSPEC*HID/4;t+=128) ((float4*)sT)[t]=((const float4*)g_T)[t];
    if(tid<HID)   sW3[tid]=W3[tid];
    if(tid<HID/2) sB2[tid]=pk2(b2g[2*tid],b2g[2*tid+1]);
    __syncthreads();
    float b3=b3g[0];
    const float C2=-4.0f*LOG2E;
    const float dk=CUTF/(NK-1);
    int unit = blockIdx.x*128+tid;
    bool act = unit < NSPEC*NSPEC*TSAMP;
    int u2 = act ? unit : 0;
    int spidx = u2/TSAMP;
    int msmp  = u2 - spidx*TSAMP;
    float d = ((float)msmp - 1.0f)*DLT;
    float xc = fminf(fmaxf(d*(1.0f/CUTF),0.f),1.f);
    float cut = (d<CUTF) ? 0.5f*(__cosf(PI_F*xc)+1.f) : 0.f;
    // ---- layer 1 ----
    ull acc[32];
    const float4* Tr=(const float4*)&sT[spidx*HID];
    #pragma unroll
    for(int q=0;q<16;q++){
        float4 t=Tr[q];
        acc[2*q]=pk2(t.x,t.y); acc[2*q+1]=pk2(t.z,t.w);
    }
    #pragma unroll 4
    for(int k=0;k<NK;k++){
        float t=d-(float)k*dk;
        float r=exp2f(C2*t*t);
        ull rd=pk2(r,r);
        const ulonglong2* wr=(const ulonglong2*)&sW1[k*HID];
        #pragma unroll
        for(int q=0;q<16;q++){
            ulonglong2 wv=wr[q];
            fma2(acc[2*q],   rd, wv.x);
            fma2(acc[2*q+1], rd, wv.y);
        }
    }
    // ---- silu in place ----
    #pragma unroll
    for(int mq=0;mq<32;mq++){
        float h0,h1; upk2(acc[mq],h0,h1);
        acc[mq]=pk2(siluf(h0),siluf(h1));
    }
    // ---- layer 2 single pass ----
    ull acc2[32];
    #pragma unroll
    for(int q=0;q<32;q++) acc2[q]=sB2[q];
    #pragma unroll
    for(int mq=0;mq<32;mq++){
        float h0,h1; upk2(acc[mq],h0,h1);
        ull hd0=pk2(h0,h0), hd1=pk2(h1,h1);
        const ulonglong2* wr0=(const ulonglong2*)&sW2[(2*mq)*HID];
        const ulonglong2* wr1=(const ulonglong2*)&sW2[(2*mq+1)*HID];
        #pragma unroll
        for(int q=0;q<16;q++){
            ulonglong2 w0=wr0[q];
            ulonglong2 w1=wr1[q];
            fma2(acc2[2*q],   hd0, w0.x);
            fma2(acc2[2*q+1], hd0, w0.y);
            fma2(acc2[2*q],   hd1, w1.x);
            fma2(acc2[2*q+1], hd1, w1.y);
        }
    }
    // ---- epilogue ----
    float e=b3;
    #pragma unroll
    for(int q=0;q<32;q++){
        float a,b; upk2(acc2[q],a,b);
        e += siluf(a)*sW3[2*q] + siluf(b)*sW3[2*q+1];
    }
    if(act) g_gtab[spidx][msmp] = e*cut;
}

// ---- k_pairE: per-pair cubic table interpolation ----
__global__ void __launch_bounds__(256) k_pairE(){
    int np=g_npairs;
    int tid=blockIdx.x*256+threadIdx.x;
    int lane=threadIdx.x&31;
    int stride=gridDim.x*256;
    const float inv = 1.0f/DLT;
    float eacc=0.f;
    for(int p=tid;p<np;p+=stride){
        unsigned pr=__ldg(&g_pairs[p]);
        int sp=(int)(pr>>22);
        int i=(int)((pr>>11)&2047u), j=(int)(pr&2047u);
        float4 pi=__ldg(&g_pos4[i]);
        float4 pj=__ldg(&g_pos4[j]);
        float dx=pi.x-pj.x, dy=pi.y-pj.y, dz=pi.z-pj.z;
        float d=sqrtf(dx*dx+dy*dy+dz*dz+1e-12f);
        float x=d*inv;                 // < 512 (list guarantees d < 5)
        int i0=(int)x;
        float t=x-(float)i0;
        const float* row=&g_gtab[sp][i0];
        float v0=__ldg(&row[0]), v1=__ldg(&row[1]), v2=__ldg(&row[2]), v3=__ldg(&row[3]);
        // Lagrange cubic through nodes at t = -1, 0, 1, 2
        float ta=t+1.f, tb=t, tc2=t-1.f, td=t-2.f;
        float g = v0*(-tb*tc2*td*(1.f/6.f))
                + v1*( ta*tc2*td*0.5f)
                + v2*(-ta*tb*td*0.5f)
                + v3*( ta*tb*tc2*(1.f/6.f));
        eacc += g;
    }
    #pragma unroll
    for(int off=16;off;off>>=1) eacc += __shfl_down_sync(0xffffffffu, eacc, off);
    if(lane==0) atomicAdd(&g_acc_pair, eacc);
}

// ---- k_coul: 128x128 tiled triangle + charge normalization/output ----
#define CTILE 128
#define NT (NATOMS/CTILE)
__global__ void __launch_bounds__(CTILE) k_coul(const float* __restrict__ pos,
    const float* __restrict__ tc, const float* __restrict__ soft_raw,
    float* __restrict__ out){
    __shared__ float4 sp[CTILE];
    __shared__ float  sq[CTILE];
    __shared__ float  red[CTILE];
    int b=blockIdx.x;
    int bi=0;
    {   int bb=b;
        while(bb >= NT-bi){ bb-=NT-bi; bi++; }
        b=bb;
    }
    int bj=bi+b;
    int t=threadIdx.x;
    float mu = g_acc_raw*(1.f/NATOMS);
    float qadd = tc[0]*(1.f/NATOMS) - mu;
    int i = bi*CTILE+t;
    float qi = g_raw[i]+qadd;
    float4 piv = make_float4(pos[3*i],pos[3*i+1],pos[3*i+2],0.f);
    {
        int j = bj*CTILE+t;
        sp[t]=make_float4(pos[3*j],pos[3*j+1],pos[3*j+2],0.f);
        sq[t]=g_raw[j]+qadd;
    }
    __syncthreads();
    float soft=log1pf(__expf(soft_raw[0]))+0.001f;
    float s2=soft*soft+1e-12f;
    float acc=0.f;
    if(bi==bj){
        out[1+i]=qi;
        for(int jj=t+1;jj<CTILE;jj++){
            float4 pj=sp[jj];
            float dx=piv.x-pj.x,dy=piv.y-pj.y,dz=piv.z-pj.z;
            acc += sq[jj]*rsqrtf(dx*dx+dy*dy+dz*dz+s2);
        }
    } else {
        for(int jj=0;jj<CTILE;jj++){
            float4 pj=sp[jj];
            float dx=piv.x-pj.x,dy=piv.y-pj.y,dz=piv.z-pj.z;
            acc += sq[jj]*rsqrtf(dx*dx+dy*dy+dz*dz+s2);
        }
    }
    red[t]=acc*qi;
    __syncthreads();
    for(int off=CTILE/2;off;off>>=1){ if(t<off) red[t]+=red[t+off]; __syncthreads(); }
    if(t==0) atomicAdd(&g_acc_lr, red[0]);
}

__global__ void k_final(const float* __restrict__ cs, float* __restrict__ out){
    out[0]=g_acc_pair + cs[0]*g_acc_lr;
}

extern "C" void kernel_launch(void* const* d_in, const int* in_sizes, int n_in,
                              void* d_out, int out_size){
    const int*   species      =(const int*)  d_in[0];
    const float* pos          =(const float*)d_in[1];
    const float* tc           =(const float*)d_in[2];
    const float* embed        =(const float*)d_in[3];
    const float* W1           =(const float*)d_in[4];
    const float* b1           =(const float*)d_in[5];
    const float* W2           =(const float*)d_in[6];
    const float* b2           =(const float*)d_in[7];
    const float* W3           =(const float*)d_in[8];
    const float* b3           =(const float*)d_in[9];
    const float* atom_bias    =(const float*)d_in[10];
    const float* cW1          =(const float*)d_in[11];
    const float* cb1          =(const float*)d_in[12];
    const float* cW2          =(const float*)d_in[13];
    const float* cb2          =(const float*)d_in[14];
    const float* cW3          =(const float*)d_in[15];
    const float* cb3          =(const float*)d_in[16];
    const float* charge_scale =(const float*)d_in[17];
    const float* coulomb_scale=(const float*)d_in[18];
    const float* soft_raw     =(const float*)d_in[19];
    float* out=(float*)d_out;

    static cudaStream_t s2;
    static cudaEvent_t evFork, evLocal, evJoin;
    static int init_done = 0;
    if(!init_done){
        cudaStreamCreateWithFlags(&s2, cudaStreamNonBlocking);
        cudaEventCreateWithFlags(&evFork,  cudaEventDisableTiming);
        cudaEventCreateWithFlags(&evLocal, cudaEventDisableTiming);
        cudaEventCreateWithFlags(&evJoin,  cudaEventDisableTiming);
        init_done = 1;
    }

    // stream0: table -> tab2 -> (wait local) pairE -> (wait coul) final
    // s2:      (wait table) local -> cmlp -> coul
    k_table <<<64,64>>>(pos,embed,W1,b1);
    cudaEventRecord(evFork, 0);

    cudaStreamWaitEvent(s2, evFork, 0);
    k_local <<<NATOMS/4,256,0,s2>>>(pos,species);
    cudaEventRecord(evLocal, s2);
    k_cmlp  <<<NATOMS/CT_M,256,0,s2>>>(species,embed,tc,cW1,cb1,cW2,cb2,cW3,cb3,charge_scale,atom_bias);
    k_coul  <<<NT*(NT+1)/2,CTILE,0,s2>>>(pos,tc,soft_raw,out);
    cudaEventRecord(evJoin, s2);

    k_tab2  <<<(NSPEC*NSPEC*TSAMP+127)/128,128>>>(W1,b2,W2,W3,b3);
    cudaStreamWaitEvent(0, evLocal, 0);
    k_pairE <<<148,256>>>();
    cudaStreamWaitEvent(0, evJoin, 0);
    k_final <<<1,1>>>(coulomb_scale,out);
}